// round 13
// baseline (speedup 1.0000x reference)
#include <cuda_runtime.h>
#include <cuda_bf16.h>
#include <math.h>
#include <float.h>
#include <stdint.h>

// Problem constants
#define B_   2
#define S_   2048
#define HID_ 768
#define H_   12
#define D_   64
#define BS_  256
#define NB_  8
#define TK_  3
#define M_   (B_ * S_)          // 4096 token rows
#define NCHUNK_ 12              // 768 / 64 K-chunks

// Scratch (device globals; no runtime allocation allowed)
__device__ float g_q[B_ * H_ * S_ * D_];
__device__ float g_k[B_ * H_ * S_ * D_];
__device__ float g_brep[B_ * H_ * NB_ * D_];
__device__ unsigned char g_mask[B_ * H_ * S_];
__device__ float g_sinT[S_ * 32];
__device__ float g_cosT[S_ * 32];

// bf16 split operands, pre-swizzled tiles (SW128, K-major rows of 128B)
__device__ __nv_bfloat16 g_ah[M_ * HID_];       // GEMM A hi (hidden, later attn out)
__device__ __nv_bfloat16 g_al[M_ * HID_];       // GEMM A lo
__device__ __nv_bfloat16 g_wh[4][HID_ * HID_];  // Wq,Wk,Wv,Wo hi
__device__ __nv_bfloat16 g_wl[4][HID_ * HID_];  // lo

// Attention operands: 64x64 tiles, tile idx = bh*32 + t64 (4096 elems/tile)
__device__ __nv_bfloat16 g_qh[B_ * H_ * S_ * D_];
__device__ __nv_bfloat16 g_ql[B_ * H_ * S_ * D_];
__device__ __nv_bfloat16 g_kh[B_ * H_ * S_ * D_];
__device__ __nv_bfloat16 g_kl[B_ * H_ * S_ * D_];
__device__ __nv_bfloat16 g_vth[B_ * H_ * S_ * D_];  // V transposed [d][key]
__device__ __nv_bfloat16 g_vtl[B_ * H_ * S_ * D_];

__device__ __forceinline__ uint32_t smem_u32(const void* p) {
    uint32_t a;
    asm("{ .reg .u64 t; cvta.to.shared.u64 t, %1; cvt.u32.u64 %0, t; }"
        : "=r"(a) : "l"(p));
    return a;
}
__device__ __forceinline__ uint32_t sw128(uint32_t off) {
    return off ^ ((off >> 3) & 0x70);
}
__device__ __forceinline__ void cp_async16(uint32_t saddr, const void* gptr) {
    asm volatile("cp.async.cg.shared.global [%0], [%1], 16;"
                 :: "r"(saddr), "l"(gptr));
}
#define CP_COMMIT() asm volatile("cp.async.commit_group;" ::: "memory")
#define CP_WAIT1()  asm volatile("cp.async.wait_group 1;" ::: "memory")
#define CP_WAIT0()  asm volatile("cp.async.wait_group 0;" ::: "memory")

// ---------------------------------------------------------------------------
// HMMA helpers
// ---------------------------------------------------------------------------
__device__ __forceinline__ void ldmatrix_x4(uint32_t& r0, uint32_t& r1,
                                            uint32_t& r2, uint32_t& r3,
                                            uint32_t addr) {
    asm volatile("ldmatrix.sync.aligned.m8n8.x4.shared.b16 {%0,%1,%2,%3}, [%4];"
                 : "=r"(r0), "=r"(r1), "=r"(r2), "=r"(r3) : "r"(addr));
}
__device__ __forceinline__ void mma16816(float* c, const uint32_t* a,
                                         uint32_t b0, uint32_t b1) {
    asm volatile(
        "mma.sync.aligned.m16n8k16.row.col.f32.bf16.bf16.f32 "
        "{%0,%1,%2,%3}, {%4,%5,%6,%7}, {%8,%9}, {%0,%1,%2,%3};"
        : "+f"(c[0]), "+f"(c[1]), "+f"(c[2]), "+f"(c[3])
        : "r"(a[0]), "r"(a[1]), "r"(a[2]), "r"(a[3]), "r"(b0), "r"(b1));
}
__device__ __forceinline__ uint32_t bf16x2_pack(float lo, float hi) {
    uint32_t r;
    asm("cvt.rn.bf16x2.f32 %0, %1, %2;" : "=r"(r) : "f"(hi), "f"(lo));
    return r;
}

// ---------------------------------------------------------------------------
// Merged input conversion + sin/cos table init (one launch).
// ---------------------------------------------------------------------------
#define NA_CONV (M_ * 384)
#define NW_CONV (HID_ * 384)
#define N_CONV_TOTAL (NA_CONV + 4 * NW_CONV)
__global__ __launch_bounds__(256) void conv_all_kernel(
    const float* __restrict__ hidden, const float* __restrict__ W0,
    const float* __restrict__ W1, const float* __restrict__ W2,
    const float* __restrict__ W3) {
    int idx = blockIdx.x * 256 + threadIdx.x;
    if (idx >= N_CONV_TOTAL) {
        int ti = idx - N_CONV_TOTAL;
        if (ti < S_ * 32) {
            int i = ti & 31;
            int s = ti >> 5;
            float inv = (float)exp(-9.210340371976184 * (double)i / 32.0);
            float ang = (float)s * inv;
            g_sinT[ti] = sinf(ang);
            g_cosT[ti] = cosf(ang);
        }
        return;
    }
    const float* src;
    __nv_bfloat16 *dh, *dl;
    int li;
    if (idx < NA_CONV) {
        src = hidden; dh = g_ah; dl = g_al; li = idx;
    } else {
        int w = (idx - NA_CONV) / NW_CONV;
        li = (idx - NA_CONV) - w * NW_CONV;
        src = (w == 0) ? W0 : (w == 1) ? W1 : (w == 2) ? W2 : W3;
        dh = g_wh[w]; dl = g_wl[w];
    }
    int rg  = li / 384;
    int col = (li - rg * 384) * 2;
    int mtile = rg >> 7;
    int r = rg & 127;
    int chunk = col >> 6;
    int cc = col & 63;
    uint32_t sw = sw128((uint32_t)(r * 128 + cc * 2));
    size_t dst_half = (size_t)(mtile * NCHUNK_ + chunk) * 8192 + (sw >> 1);
    float2 v = *(const float2*)(src + (size_t)rg * HID_ + col);
    __nv_bfloat16 h0 = __float2bfloat16(v.x);
    __nv_bfloat16 h1 = __float2bfloat16(v.y);
    __nv_bfloat16 l0 = __float2bfloat16(v.x - __bfloat162float(h0));
    __nv_bfloat16 l1 = __float2bfloat16(v.y - __bfloat162float(h1));
    *(__nv_bfloat162*)(dh + dst_half) = __nv_bfloat162(h0, h1);
    *(__nv_bfloat162*)(dl + dst_half) = __nv_bfloat162(l0, l1);
}

// ---------------------------------------------------------------------------
// HMMA GEMM, cp.async double-buffered.  (Exact round-9 configuration.)
// ---------------------------------------------------------------------------
#define T_AH 0
#define T_AL 16384
#define T_BH 32768
#define T_BL 49152
#define G_STAGE 65536
#define GEMM_SMEM_BYTES (2 * G_STAGE)

template <int MODE>
__global__ __launch_bounds__(256) void mma_gemm_kernel(float* __restrict__ out) {
    extern __shared__ char smem[];
    const uint32_t sb = smem_u32(smem);
    const int tid = threadIdx.x;
    const int wid = tid >> 5, lid = tid & 31;
    const int bn = blockIdx.x;
    const int bm = blockIdx.y;
    const int wm = (wid & 3) * 32;
    const int wn = (wid >> 2) * 64;
    const int z = (MODE == 0) ? blockIdx.z : 3;

    const __nv_bfloat16 *Ah = g_ah, *Al = g_al;
    const __nv_bfloat16 *Bh = g_wh[z], *Bl = g_wl[z];

    float acc[2][8][4];
#pragma unroll
    for (int i = 0; i < 2; ++i)
#pragma unroll
        for (int j = 0; j < 8; ++j)
#pragma unroll
            for (int r = 0; r < 4; ++r) acc[i][j][r] = 0.0f;

    const size_t a_base = (size_t)bm * NCHUNK_ * 8192;
    const size_t b_base = (size_t)bn * NCHUNK_ * 8192;

    const int a_row = (lid & 15);
    const int a_kc8 = (lid >> 4) << 3;
    const int b_row = (lid & 7) + ((lid >> 4) << 3);
    const int b_kc8 = ((lid >> 3) & 1) << 3;

    auto issue_chunk = [&](int c, int st) {
        uint32_t base = sb + st * G_STAGE;
        const char* s0 = (const char*)(Ah + a_base + (size_t)c * 8192);
        const char* s1 = (const char*)(Al + a_base + (size_t)c * 8192);
        const char* s2 = (const char*)(Bh + b_base + (size_t)c * 8192);
        const char* s3 = (const char*)(Bl + b_base + (size_t)c * 8192);
#pragma unroll
        for (int i = 0; i < 4; ++i) {
            int o = (tid + i * 256) * 16;
            cp_async16(base + T_AH + o, s0 + o);
            cp_async16(base + T_AL + o, s1 + o);
            cp_async16(base + T_BH + o, s2 + o);
            cp_async16(base + T_BL + o, s3 + o);
        }
    };

    issue_chunk(0, 0);
    CP_COMMIT();

    for (int c = 0; c < NCHUNK_; ++c) {
        const int st = c & 1;
        if (c + 1 < NCHUNK_) {
            issue_chunk(c + 1, (c + 1) & 1);
            CP_COMMIT();
            CP_WAIT1();
        } else {
            CP_WAIT0();
        }
        __syncthreads();
        const uint32_t stb = sb + st * G_STAGE;
#pragma unroll
        for (int ks = 0; ks < 4; ++ks) {
            const int k0 = ks * 16;
            uint32_t fah[2][4], fal[2][4];
#pragma unroll
            for (int i = 0; i < 2; ++i) {
                uint32_t sw = sw128((uint32_t)((wm + 16 * i + a_row) * 128 +
                                               (k0 + a_kc8) * 2));
                ldmatrix_x4(fah[i][0], fah[i][1], fah[i][2], fah[i][3],
                            stb + T_AH + sw);
                ldmatrix_x4(fal[i][0], fal[i][1], fal[i][2], fal[i][3],
                            stb + T_AL + sw);
            }
            uint32_t fbh[4][4], fbl[4][4];
#pragma unroll
            for (int jp = 0; jp < 4; ++jp) {
                uint32_t sw = sw128((uint32_t)((wn + 16 * jp + b_row) * 128 +
                                               (k0 + b_kc8) * 2));
                ldmatrix_x4(fbh[jp][0], fbh[jp][1], fbh[jp][2], fbh[jp][3],
                            stb + T_BH + sw);
                ldmatrix_x4(fbl[jp][0], fbl[jp][1], fbl[jp][2], fbl[jp][3],
                            stb + T_BL + sw);
            }
#pragma unroll
            for (int i = 0; i < 2; ++i)
#pragma unroll
                for (int j = 0; j < 8; ++j) {
                    int jp = j >> 1, rr = (j & 1) * 2;
                    mma16816(acc[i][j], fah[i], fbh[jp][rr], fbh[jp][rr + 1]);
                    mma16816(acc[i][j], fah[i], fbl[jp][rr], fbl[jp][rr + 1]);
                    mma16816(acc[i][j], fal[i], fbh[jp][rr], fbh[jp][rr + 1]);
                }
        }
        __syncthreads();
    }

    const int g = lid >> 2, t = lid & 3;

    // Fused RoPE for Q/K (MODE 0, z<2): lane holds cols d and d+32 at j, j+4.
    if (MODE == 0 && z < 2) {
#pragma unroll
        for (int i = 0; i < 2; ++i) {
#pragma unroll
            for (int half = 0; half < 2; ++half) {
                int row = bm * 128 + wm + 16 * i + g + half * 8;
                int s = row & (S_ - 1);
#pragma unroll
                for (int j = 0; j < 4; ++j) {
#pragma unroll
                    for (int e = 0; e < 2; ++e) {
                        int dd = 8 * j + 2 * t + e;   // < 32
                        float cs = g_cosT[s * 32 + dd];
                        float sn = g_sinT[s * 32 + dd];
                        float x1 = acc[i][j][2 * half + e];
                        float x2 = acc[i][j + 4][2 * half + e];
                        acc[i][j][2 * half + e]     = x1 * cs - x2 * sn;
                        acc[i][j + 4][2 * half + e] = x2 * cs + x1 * sn;
                    }
                }
            }
        }
    }

#pragma unroll
    for (int i = 0; i < 2; ++i) {
#pragma unroll
        for (int j = 0; j < 8; ++j) {
            int row0 = bm * 128 + wm + 16 * i + g;
            int n = bn * 128 + wn + 8 * j + 2 * t;
#pragma unroll
            for (int half = 0; half < 2; ++half) {
                int row = row0 + half * 8;
                float2 v = make_float2(acc[i][j][half * 2 + 0],
                                       acc[i][j][half * 2 + 1]);
                if (MODE == 0) {
                    int bb = row >> 11;
                    int ss = row & (S_ - 1);
                    int hh = n >> 6;
                    int dd = n & 63;
                    __nv_bfloat16 h0 = __float2bfloat16(v.x);
                    __nv_bfloat16 h1 = __float2bfloat16(v.y);
                    __nv_bfloat16 l0 = __float2bfloat16(v.x - __bfloat162float(h0));
                    __nv_bfloat16 l1 = __float2bfloat16(v.y - __bfloat162float(h1));
                    size_t tile = (size_t)((bb * H_ + hh) * 32 + (ss >> 6)) * 4096;
                    if (z < 2) {
                        float* dst = (z == 0) ? g_q : g_k;
                        *(float2*)(dst + (((size_t)(bb * H_ + hh) * S_ + ss) << 6) + dd) = v;
                        __nv_bfloat16* th = (z == 0) ? g_qh : g_kh;
                        __nv_bfloat16* tl = (z == 0) ? g_ql : g_kl;
                        uint32_t sw = sw128((uint32_t)((ss & 63) * 128 + dd * 2));
                        *(__nv_bfloat162*)(th + tile + (sw >> 1)) = __nv_bfloat162(h0, h1);
                        *(__nv_bfloat162*)(tl + tile + (sw >> 1)) = __nv_bfloat162(l0, l1);
                    } else {
                        // V: transposed [d][key] bf16 tiles only
                        int rr2 = ss & 63;
                        uint32_t sw0 = sw128((uint32_t)(dd * 128 + rr2 * 2));
                        uint32_t sw1 = sw128((uint32_t)((dd + 1) * 128 + rr2 * 2));
                        g_vth[tile + (sw0 >> 1)] = h0;
                        g_vtl[tile + (sw0 >> 1)] = l0;
                        g_vth[tile + (sw1 >> 1)] = h1;
                        g_vtl[tile + (sw1 >> 1)] = l1;
                    }
                } else {
                    *(float2*)(out + (size_t)row * HID_ + n) = v;
                }
            }
        }
    }
}

// ---------------------------------------------------------------------------
// Block representatives: mean of roped K over 256-token blocks.  512 threads.
// ---------------------------------------------------------------------------
__global__ __launch_bounds__(512) void brep_kernel() {
    __shared__ float red[8][64];
    int blk = blockIdx.x;          // bh*8 + nb
    int bh = blk >> 3;
    int nbk = blk & 7;
    int d = threadIdx.x & 63;
    int qd = threadIdx.x >> 6;     // 0..7
    const float* kp = g_k + ((size_t)bh * S_ + nbk * BS_ + qd * 32) * 64 + d;
    float sum = 0.0f;
#pragma unroll 8
    for (int i = 0; i < 32; ++i) sum += kp[(size_t)i * 64];
    red[qd][d] = sum;
    __syncthreads();
    if (qd == 0) {
        float t = 0.0f;
#pragma unroll
        for (int i = 0; i < 8; ++i) t += red[i][d];
        g_brep[(size_t)blk * 64 + d] = t * (1.0f / 256.0f);
    }
}

// ---------------------------------------------------------------------------
// Top-3 selection: Q rows read directly to registers (no Qsh staging).
// 256 threads, one query each; Bsh (2KB) only smem.
// ---------------------------------------------------------------------------
__global__ __launch_bounds__(256) void select_kernel() {
    __shared__ float Bsh[NB_ * 64];
    const int tid = threadIdx.x;
    const int qidx = blockIdx.x * 256 + tid;
    const int bh = qidx >> 11;

    for (int off = tid; off < NB_ * 64; off += 256)
        Bsh[off] = g_brep[(size_t)bh * (NB_ * 64) + off];
    __syncthreads();

    float qreg[64];
    const float4* qp = (const float4*)(g_q + (size_t)qidx * 64);
#pragma unroll
    for (int i = 0; i < 16; ++i) {
        float4 v = qp[i];
        qreg[i * 4 + 0] = v.x;
        qreg[i * 4 + 1] = v.y;
        qreg[i * 4 + 2] = v.z;
        qreg[i * 4 + 3] = v.w;
    }

    int s = qidx & (S_ - 1);
    int cur = s >> 8;

    float sc[NB_];
#pragma unroll
    for (int j = 0; j < NB_; ++j) {
        if (j > cur) { sc[j] = -INFINITY; continue; }
        if (j == cur) { sc[j] = 3.402823466e38f; continue; }
        float dd = 0.0f;
#pragma unroll 8
        for (int d = 0; d < 64; ++d) dd = fmaf(qreg[d], Bsh[j * 64 + d], dd);
        sc[j] = dd;
    }

    unsigned msk = 0;
    bool used[NB_];
#pragma unroll
    for (int j = 0; j < NB_; ++j) used[j] = false;
#pragma unroll
    for (int t = 0; t < TK_; ++t) {
        int bi = -1; float bv = 0.0f;
#pragma unroll
        for (int j = 0; j < NB_; ++j) {
            if (!used[j] && (bi < 0 || sc[j] > bv)) { bi = j; bv = sc[j]; }
        }
        used[bi] = true;
        msk |= 1u << bi;
    }
    g_mask[qidx] = (unsigned char)msk;
}

// ---------------------------------------------------------------------------
// Sparse flash attention on HMMA (bf16x3), cp.async double-buffered K/V.
// 128 queries per CTA (8 warps x m16) — KV streamed once per 128 queries.
// grid = (16, 12, 2), 256 threads, qt reversed (heavy tiles first).
// smem 64KB: Q hi/lo (32KB) overlays KV stage 0; 2 stages x 32KB.
// Inner-loop arithmetic identical to round 9.
// ---------------------------------------------------------------------------
#define A_STAGE 32768
#define ATTN_SMEM (2 * A_STAGE)

__global__ __launch_bounds__(256) void attn_kernel() {
    extern __shared__ char smem[];
    const uint32_t sb = smem_u32(smem);
    const int tid = threadIdx.x;
    const int wid = tid >> 5, lid = tid & 31;
    const int qt = (int)(gridDim.x - 1 - blockIdx.x);   // heavy tiles first
    const int h = blockIdx.y, b = blockIdx.z;
    const int q0 = qt * 128;
    const int bh = b * H_ + h;
    const int wq = wid * 16;            // 0..112

    // Load Q (two adjacent 64x64 tiles, contiguous in gmem) into stage-0:
    // [qh 16KB | ql 16KB]
    {
        const uint4* s0 = (const uint4*)(g_qh + (size_t)(bh * 32 + qt * 2) * 4096);
        const uint4* s1 = (const uint4*)(g_ql + (size_t)(bh * 32 + qt * 2) * 4096);
        uint4* d0 = (uint4*)(smem);
        uint4* d1 = (uint4*)(smem + 16384);
#pragma unroll
        for (int i = 0; i < 4; ++i) {
            int o = tid + i * 256;
            d0[o] = s0[o];
            d1[o] = s1[o];
        }
    }
    __syncthreads();

    const int a_row = lid & 15;
    const int a_k8 = (lid >> 4) << 3;
    const int b_row = (lid & 7) + ((lid >> 4) << 3);
    const int b_k8 = ((lid >> 3) & 1) << 3;
    const int qtile = wq >> 6;          // 0 or 1
    const int qrow64 = wq & 63;
    uint32_t fqh[4][4], fql[4][4];
#pragma unroll
    for (int ks = 0; ks < 4; ++ks) {
        uint32_t sw = sw128((uint32_t)((qrow64 + a_row) * 128 + (ks * 16 + a_k8) * 2));
        ldmatrix_x4(fqh[ks][0], fqh[ks][1], fqh[ks][2], fqh[ks][3],
                    sb + qtile * 8192 + sw);
        ldmatrix_x4(fql[ks][0], fql[ks][1], fql[ks][2], fql[ks][3],
                    sb + 16384 + qtile * 8192 + sw);
    }
    __syncthreads();   // all warps done reading Q before stage 0 is overwritten

    const int g = lid >> 2;
    const int qq = (lid & 3) * 2;
    const int r0 = q0 + wq + g;
    const int r1 = r0 + 8;
    const unsigned msk0 = g_mask[(size_t)bh * S_ + r0];
    const unsigned msk1 = g_mask[(size_t)bh * S_ + r1];

    const int cur = q0 >> 8;            // uniform across the 128-query tile
    const int nkt = ((cur >= 2) ? (cur + 1) : 3) * 4;

    float mrow0 = -INFINITY, mrow1 = -INFINITY, lrow0 = 0.0f, lrow1 = 0.0f;
    float acc_o[8][4];
#pragma unroll
    for (int j = 0; j < 8; ++j)
#pragma unroll
        for (int r = 0; r < 4; ++r) acc_o[j][r] = 0.0f;

    auto issue_kv = [&](int kt, int st) {
        size_t tb = (size_t)(bh * 32 + kt) * 4096;
        uint32_t base = sb + st * A_STAGE;
        const char* s0 = (const char*)(g_kh + tb);
        const char* s1 = (const char*)(g_kl + tb);
        const char* s2 = (const char*)(g_vth + tb);
        const char* s3 = (const char*)(g_vtl + tb);
#pragma unroll
        for (int i = 0; i < 2; ++i) {
            int o = (tid + i * 256) * 16;
            cp_async16(base + 0 + o, s0 + o);
            cp_async16(base + 8192 + o, s1 + o);
            cp_async16(base + 16384 + o, s2 + o);
            cp_async16(base + 24576 + o, s3 + o);
        }
    };

    issue_kv(0, 0);
    CP_COMMIT();

    for (int kt = 0; kt < nkt; ++kt) {
        const int k0 = kt * 64;
        const int jb = kt >> 2;
        const int st = kt & 1;
        if (kt + 1 < nkt) {
            issue_kv(kt + 1, (kt + 1) & 1);
            CP_COMMIT();
            CP_WAIT1();
        } else {
            CP_WAIT0();
        }
        __syncthreads();
        const uint32_t kb = sb + st * A_STAGE;

        // S = Q K^T (bf16x3)
        float s[8][4];
#pragma unroll
        for (int j = 0; j < 8; ++j)
#pragma unroll
            for (int r = 0; r < 4; ++r) s[j][r] = 0.0f;
#pragma unroll
        for (int ks = 0; ks < 4; ++ks) {
            uint32_t fkh[4][4], fkl[4][4];
#pragma unroll
            for (int jp = 0; jp < 4; ++jp) {
                uint32_t sw = sw128((uint32_t)((jp * 16 + b_row) * 128 +
                                               (ks * 16 + b_k8) * 2));
                ldmatrix_x4(fkh[jp][0], fkh[jp][1], fkh[jp][2], fkh[jp][3],
                            kb + 0 + sw);
                ldmatrix_x4(fkl[jp][0], fkl[jp][1], fkl[jp][2], fkl[jp][3],
                            kb + 8192 + sw);
            }
#pragma unroll
            for (int j = 0; j < 8; ++j) {
                int jp = j >> 1, rr = (j & 1) * 2;
                mma16816(s[j], fqh[ks], fkh[jp][rr], fkh[jp][rr + 1]);
                mma16816(s[j], fqh[ks], fkl[jp][rr], fkl[jp][rr + 1]);
                mma16816(s[j], fql[ks], fkh[jp][rr], fkh[jp][rr + 1]);
            }
        }

        // Mask + scale + online softmax (round-9 form)
        const bool sel0 = (msk0 >> jb) & 1u;
        const bool sel1 = (msk1 >> jb) & 1u;
        float mx0 = -INFINITY, mx1 = -INFINITY;
#pragma unroll
        for (int j = 0; j < 8; ++j) {
#pragma unroll
            for (int e = 0; e < 2; ++e) {
                int kg = k0 + j * 8 + qq + e;
                bool v0 = sel0 && (jb != cur || kg <= r0);
                bool v1 = sel1 && (jb != cur || kg <= r1);
                float s0v = v0 ? s[j][e] * 0.125f : -INFINITY;
                float s1v = v1 ? s[j][2 + e] * 0.125f : -INFINITY;
                s[j][e] = s0v;
                s[j][2 + e] = s1v;
                mx0 = fmaxf(mx0, s0v);
                mx1 = fmaxf(mx1, s1v);
            }
        }
#pragma unroll
        for (int off = 1; off <= 2; off <<= 1) {
            mx0 = fmaxf(mx0, __shfl_xor_sync(0xffffffffu, mx0, off));
            mx1 = fmaxf(mx1, __shfl_xor_sync(0xffffffffu, mx1, off));
        }
        float newm0 = fmaxf(mrow0, mx0);
        float newm1 = fmaxf(mrow1, mx1);
        float fac0 = (mrow0 == -INFINITY) ? 0.0f : __expf(mrow0 - newm0);
        float fac1 = (mrow1 == -INFINITY) ? 0.0f : __expf(mrow1 - newm1);
        float rs0 = 0.0f, rs1 = 0.0f;
#pragma unroll
        for (int j = 0; j < 8; ++j) {
#pragma unroll
            for (int e = 0; e < 2; ++e) {
                float p0 = (s[j][e] == -INFINITY) ? 0.0f : __expf(s[j][e] - newm0);
                float p1 = (s[j][2 + e] == -INFINITY) ? 0.0f : __expf(s[j][2 + e] - newm1);
                s[j][e] = p0;
                s[j][2 + e] = p1;
                rs0 += p0;
                rs1 += p1;
            }
        }
#pragma unroll
        for (int off = 1; off <= 2; off <<= 1) {
            rs0 += __shfl_xor_sync(0xffffffffu, rs0, off);
            rs1 += __shfl_xor_sync(0xffffffffu, rs1, off);
        }
        lrow0 = lrow0 * fac0 + rs0;
        lrow1 = lrow1 * fac1 + rs1;
        mrow0 = newm0;
        mrow1 = newm1;
#pragma unroll
        for (int j = 0; j < 8; ++j) {
            acc_o[j][0] *= fac0;
            acc_o[j][1] *= fac0;
            acc_o[j][2] *= fac1;
            acc_o[j][3] *= fac1;
        }

        // acc_o += P V  (round-9 form: cvt round-trip hi, then lo)
#pragma unroll
        for (int j0 = 0; j0 < 4; ++j0) {
            const int j = 2 * j0;
            float h00 = __bfloat162float(__float2bfloat16(s[j][0]));
            float h01 = __bfloat162float(__float2bfloat16(s[j][1]));
            float h02 = __bfloat162float(__float2bfloat16(s[j][2]));
            float h03 = __bfloat162float(__float2bfloat16(s[j][3]));
            float h10 = __bfloat162float(__float2bfloat16(s[j + 1][0]));
            float h11 = __bfloat162float(__float2bfloat16(s[j + 1][1]));
            float h12 = __bfloat162float(__float2bfloat16(s[j + 1][2]));
            float h13 = __bfloat162float(__float2bfloat16(s[j + 1][3]));
            uint32_t ph[4], pl[4];
            ph[0] = bf16x2_pack(s[j][0], s[j][1]);
            ph[1] = bf16x2_pack(s[j][2], s[j][3]);
            ph[2] = bf16x2_pack(s[j + 1][0], s[j + 1][1]);
            ph[3] = bf16x2_pack(s[j + 1][2], s[j + 1][3]);
            pl[0] = bf16x2_pack(s[j][0] - h00, s[j][1] - h01);
            pl[1] = bf16x2_pack(s[j][2] - h02, s[j][3] - h03);
            pl[2] = bf16x2_pack(s[j + 1][0] - h10, s[j + 1][1] - h11);
            pl[3] = bf16x2_pack(s[j + 1][2] - h12, s[j + 1][3] - h13);

            uint32_t fvh[4][4], fvl[4][4];
#pragma unroll
            for (int jp = 0; jp < 4; ++jp) {
                uint32_t sw = sw128((uint32_t)((jp * 16 + b_row) * 128 +
                                               (j0 * 16 + b_k8) * 2));
                ldmatrix_x4(fvh[jp][0], fvh[jp][1], fvh[jp][2], fvh[jp][3],
                            kb + 16384 + sw);
                ldmatrix_x4(fvl[jp][0], fvl[jp][1], fvl[jp][2], fvl[jp][3],
                            kb + 24576 + sw);
            }
#pragma unroll
            for (int jn = 0; jn < 8; ++jn) {
                int jp = jn >> 1, rr = (jn & 1) * 2;
                mma16816(acc_o[jn], ph, fvh[jp][rr], fvh[jp][rr + 1]);
                mma16816(acc_o[jn], ph, fvl[jp][rr], fvl[jp][rr + 1]);
                mma16816(acc_o[jn], pl, fvh[jp][rr], fvh[jp][rr + 1]);
            }
        }
        __syncthreads();
    }

    // Epilogue: normalize, split to bf16 hi/lo, write O-proj A-tiles directly.
    float inv0 = 1.0f / lrow0;
    float inv1 = 1.0f / lrow1;
#pragma unroll
    for (int j = 0; j < 8; ++j) {
        int n = j * 8 + qq;              // 0..63, even
#pragma unroll
        for (int half = 0; half < 2; ++half) {
            int rg = b * S_ + (half ? r1 : r0);     // token row
            float inv = half ? inv1 : inv0;
            float vx = acc_o[j][half * 2 + 0] * inv;
            float vy = acc_o[j][half * 2 + 1] * inv;
            __nv_bfloat16 h0 = __float2bfloat16(vx);
            __nv_bfloat16 h1 = __float2bfloat16(vy);
            __nv_bfloat16 l0 = __float2bfloat16(vx - __bfloat162float(h0));
            __nv_bfloat16 l1 = __float2bfloat16(vy - __bfloat162float(h1));
            int mtile = rg >> 7;
            int r = rg & 127;
            uint32_t sw = sw128((uint32_t)(r * 128 + n * 2));
            size_t dst_half = (size_t)(mtile * NCHUNK_ + h) * 8192 + (sw >> 1);
            *(__nv_bfloat162*)(g_ah + dst_half) = __nv_bfloat162(h0, h1);
            *(__nv_bfloat162*)(g_al + dst_half) = __nv_bfloat162(l0, l1);
        }
    }
}

// ---------------------------------------------------------------------------
extern "C" void kernel_launch(void* const* d_in, const int* in_sizes, int n_in,
                              void* d_out, int out_size) {
    const float* hidden = (const float*)d_in[0];
    const float* Wq = (const float*)d_in[1];
    const float* Wk = (const float*)d_in[2];
    const float* Wv = (const float*)d_in[3];
    const float* Wo = (const float*)d_in[4];

    static bool attr_done = false;
    if (!attr_done) {
        cudaFuncSetAttribute(mma_gemm_kernel<0>,
                             cudaFuncAttributeMaxDynamicSharedMemorySize,
                             GEMM_SMEM_BYTES);
        cudaFuncSetAttribute(mma_gemm_kernel<1>,
                             cudaFuncAttributeMaxDynamicSharedMemorySize,
                             GEMM_SMEM_BYTES);
        cudaFuncSetAttribute(attn_kernel,
                             cudaFuncAttributeMaxDynamicSharedMemorySize,
                             ATTN_SMEM);
        attr_done = true;
    }

    // Conversion + sin/cos tables in ONE launch
    conv_all_kernel<<<(N_CONV_TOTAL + S_ * 32 + 255) / 256, 256>>>(
        hidden, Wq, Wk, Wv, Wo);

    // QKV projections (HMMA): fused RoPE, bf16 attn tiles, V transposed bf16
    mma_gemm_kernel<0><<<dim3(HID_ / 128, M_ / 128, 3), 256, GEMM_SMEM_BYTES>>>(nullptr);

    brep_kernel<<<B_ * H_ * NB_, 512>>>();
    select_kernel<<<B_ * H_ * S_ / 256, 256>>>();

    attn_kernel<<<dim3(S_ / 128, H_, B_), 256, ATTN_SMEM>>>();

    // O projection straight from attention's bf16 tiles into d_out
    mma_gemm_kernel<1><<<dim3(HID_ / 128, M_ / 128), 256, GEMM_SMEM_BYTES>>>((float*)d_out);
}

// round 14
// speedup vs baseline: 1.1389x; 1.1389x over previous
#include <cuda_runtime.h>
#include <cuda_bf16.h>
#include <math.h>
#include <float.h>
#include <stdint.h>

// Problem constants
#define B_   2
#define S_   2048
#define HID_ 768
#define H_   12
#define D_   64
#define BS_  256
#define NB_  8
#define TK_  3
#define M_   (B_ * S_)          // 4096 token rows
#define NCHUNK_ 12              // 768 / 64 K-chunks

// Scratch (device globals; no runtime allocation allowed)
__device__ float g_q[B_ * H_ * S_ * D_];
__device__ float g_k[B_ * H_ * S_ * D_];
__device__ float g_brep[B_ * H_ * NB_ * D_];
__device__ unsigned char g_mask[B_ * H_ * S_];
__device__ float g_sinT[S_ * 32];
__device__ float g_cosT[S_ * 32];

// bf16 split operands, pre-swizzled tiles (SW128, K-major rows of 128B)
__device__ __nv_bfloat16 g_ah[M_ * HID_];       // GEMM A hi (hidden, later attn out)
__device__ __nv_bfloat16 g_al[M_ * HID_];       // GEMM A lo
__device__ __nv_bfloat16 g_wh[4][HID_ * HID_];  // Wq,Wk,Wv,Wo hi
__device__ __nv_bfloat16 g_wl[4][HID_ * HID_];  // lo

// Attention operands: 64x64 tiles, tile idx = bh*32 + t64 (4096 elems/tile)
__device__ __nv_bfloat16 g_qh[B_ * H_ * S_ * D_];
__device__ __nv_bfloat16 g_ql[B_ * H_ * S_ * D_];
__device__ __nv_bfloat16 g_kh[B_ * H_ * S_ * D_];
__device__ __nv_bfloat16 g_kl[B_ * H_ * S_ * D_];
__device__ __nv_bfloat16 g_vth[B_ * H_ * S_ * D_];  // V transposed [d][key]
__device__ __nv_bfloat16 g_vtl[B_ * H_ * S_ * D_];

__device__ __forceinline__ uint32_t smem_u32(const void* p) {
    uint32_t a;
    asm("{ .reg .u64 t; cvta.to.shared.u64 t, %1; cvt.u32.u64 %0, t; }"
        : "=r"(a) : "l"(p));
    return a;
}
__device__ __forceinline__ uint32_t sw128(uint32_t off) {
    return off ^ ((off >> 3) & 0x70);
}
__device__ __forceinline__ void cp_async16(uint32_t saddr, const void* gptr) {
    asm volatile("cp.async.cg.shared.global [%0], [%1], 16;"
                 :: "r"(saddr), "l"(gptr));
}
#define CP_COMMIT() asm volatile("cp.async.commit_group;" ::: "memory")
#define CP_WAIT1()  asm volatile("cp.async.wait_group 1;" ::: "memory")
#define CP_WAIT0()  asm volatile("cp.async.wait_group 0;" ::: "memory")

// ---------------------------------------------------------------------------
// HMMA helpers
// ---------------------------------------------------------------------------
__device__ __forceinline__ void ldmatrix_x4(uint32_t& r0, uint32_t& r1,
                                            uint32_t& r2, uint32_t& r3,
                                            uint32_t addr) {
    asm volatile("ldmatrix.sync.aligned.m8n8.x4.shared.b16 {%0,%1,%2,%3}, [%4];"
                 : "=r"(r0), "=r"(r1), "=r"(r2), "=r"(r3) : "r"(addr));
}
__device__ __forceinline__ void mma16816(float* c, const uint32_t* a,
                                         uint32_t b0, uint32_t b1) {
    asm volatile(
        "mma.sync.aligned.m16n8k16.row.col.f32.bf16.bf16.f32 "
        "{%0,%1,%2,%3}, {%4,%5,%6,%7}, {%8,%9}, {%0,%1,%2,%3};"
        : "+f"(c[0]), "+f"(c[1]), "+f"(c[2]), "+f"(c[3])
        : "r"(a[0]), "r"(a[1]), "r"(a[2]), "r"(a[3]), "r"(b0), "r"(b1));
}
__device__ __forceinline__ uint32_t bf16x2_pack(float lo, float hi) {
    uint32_t r;
    asm("cvt.rn.bf16x2.f32 %0, %1, %2;" : "=r"(r) : "f"(hi), "f"(lo));
    return r;
}

// ---------------------------------------------------------------------------
// Merged input conversion + sin/cos table init (one launch).
// ---------------------------------------------------------------------------
#define NA_CONV (M_ * 384)
#define NW_CONV (HID_ * 384)
#define N_CONV_TOTAL (NA_CONV + 4 * NW_CONV)
__global__ __launch_bounds__(256) void conv_all_kernel(
    const float* __restrict__ hidden, const float* __restrict__ W0,
    const float* __restrict__ W1, const float* __restrict__ W2,
    const float* __restrict__ W3) {
    int idx = blockIdx.x * 256 + threadIdx.x;
    if (idx >= N_CONV_TOTAL) {
        int ti = idx - N_CONV_TOTAL;
        if (ti < S_ * 32) {
            int i = ti & 31;
            int s = ti >> 5;
            float inv = (float)exp(-9.210340371976184 * (double)i / 32.0);
            float ang = (float)s * inv;
            g_sinT[ti] = sinf(ang);
            g_cosT[ti] = cosf(ang);
        }
        return;
    }
    const float* src;
    __nv_bfloat16 *dh, *dl;
    int li;
    if (idx < NA_CONV) {
        src = hidden; dh = g_ah; dl = g_al; li = idx;
    } else {
        int w = (idx - NA_CONV) / NW_CONV;
        li = (idx - NA_CONV) - w * NW_CONV;
        src = (w == 0) ? W0 : (w == 1) ? W1 : (w == 2) ? W2 : W3;
        dh = g_wh[w]; dl = g_wl[w];
    }
    int rg  = li / 384;
    int col = (li - rg * 384) * 2;
    int mtile = rg >> 7;
    int r = rg & 127;
    int chunk = col >> 6;
    int cc = col & 63;
    uint32_t sw = sw128((uint32_t)(r * 128 + cc * 2));
    size_t dst_half = (size_t)(mtile * NCHUNK_ + chunk) * 8192 + (sw >> 1);
    float2 v = *(const float2*)(src + (size_t)rg * HID_ + col);
    __nv_bfloat16 h0 = __float2bfloat16(v.x);
    __nv_bfloat16 h1 = __float2bfloat16(v.y);
    __nv_bfloat16 l0 = __float2bfloat16(v.x - __bfloat162float(h0));
    __nv_bfloat16 l1 = __float2bfloat16(v.y - __bfloat162float(h1));
    *(__nv_bfloat162*)(dh + dst_half) = __nv_bfloat162(h0, h1);
    *(__nv_bfloat162*)(dl + dst_half) = __nv_bfloat162(l0, l1);
}

// ---------------------------------------------------------------------------
// HMMA GEMM, cp.async double-buffered.  (Exact round-9 configuration.)
// ---------------------------------------------------------------------------
#define T_AH 0
#define T_AL 16384
#define T_BH 32768
#define T_BL 49152
#define G_STAGE 65536
#define GEMM_SMEM_BYTES (2 * G_STAGE)

template <int MODE>
__global__ __launch_bounds__(256) void mma_gemm_kernel(float* __restrict__ out) {
    extern __shared__ char smem[];
    const uint32_t sb = smem_u32(smem);
    const int tid = threadIdx.x;
    const int wid = tid >> 5, lid = tid & 31;
    const int bn = blockIdx.x;
    const int bm = blockIdx.y;
    const int wm = (wid & 3) * 32;
    const int wn = (wid >> 2) * 64;
    const int z = (MODE == 0) ? blockIdx.z : 3;

    const __nv_bfloat16 *Ah = g_ah, *Al = g_al;
    const __nv_bfloat16 *Bh = g_wh[z], *Bl = g_wl[z];

    float acc[2][8][4];
#pragma unroll
    for (int i = 0; i < 2; ++i)
#pragma unroll
        for (int j = 0; j < 8; ++j)
#pragma unroll
            for (int r = 0; r < 4; ++r) acc[i][j][r] = 0.0f;

    const size_t a_base = (size_t)bm * NCHUNK_ * 8192;
    const size_t b_base = (size_t)bn * NCHUNK_ * 8192;

    const int a_row = (lid & 15);
    const int a_kc8 = (lid >> 4) << 3;
    const int b_row = (lid & 7) + ((lid >> 4) << 3);
    const int b_kc8 = ((lid >> 3) & 1) << 3;

    auto issue_chunk = [&](int c, int st) {
        uint32_t base = sb + st * G_STAGE;
        const char* s0 = (const char*)(Ah + a_base + (size_t)c * 8192);
        const char* s1 = (const char*)(Al + a_base + (size_t)c * 8192);
        const char* s2 = (const char*)(Bh + b_base + (size_t)c * 8192);
        const char* s3 = (const char*)(Bl + b_base + (size_t)c * 8192);
#pragma unroll
        for (int i = 0; i < 4; ++i) {
            int o = (tid + i * 256) * 16;
            cp_async16(base + T_AH + o, s0 + o);
            cp_async16(base + T_AL + o, s1 + o);
            cp_async16(base + T_BH + o, s2 + o);
            cp_async16(base + T_BL + o, s3 + o);
        }
    };

    issue_chunk(0, 0);
    CP_COMMIT();

    for (int c = 0; c < NCHUNK_; ++c) {
        const int st = c & 1;
        if (c + 1 < NCHUNK_) {
            issue_chunk(c + 1, (c + 1) & 1);
            CP_COMMIT();
            CP_WAIT1();
        } else {
            CP_WAIT0();
        }
        __syncthreads();
        const uint32_t stb = sb + st * G_STAGE;
#pragma unroll
        for (int ks = 0; ks < 4; ++ks) {
            const int k0 = ks * 16;
            uint32_t fah[2][4], fal[2][4];
#pragma unroll
            for (int i = 0; i < 2; ++i) {
                uint32_t sw = sw128((uint32_t)((wm + 16 * i + a_row) * 128 +
                                               (k0 + a_kc8) * 2));
                ldmatrix_x4(fah[i][0], fah[i][1], fah[i][2], fah[i][3],
                            stb + T_AH + sw);
                ldmatrix_x4(fal[i][0], fal[i][1], fal[i][2], fal[i][3],
                            stb + T_AL + sw);
            }
            uint32_t fbh[4][4], fbl[4][4];
#pragma unroll
            for (int jp = 0; jp < 4; ++jp) {
                uint32_t sw = sw128((uint32_t)((wn + 16 * jp + b_row) * 128 +
                                               (k0 + b_kc8) * 2));
                ldmatrix_x4(fbh[jp][0], fbh[jp][1], fbh[jp][2], fbh[jp][3],
                            stb + T_BH + sw);
                ldmatrix_x4(fbl[jp][0], fbl[jp][1], fbl[jp][2], fbl[jp][3],
                            stb + T_BL + sw);
            }
#pragma unroll
            for (int i = 0; i < 2; ++i)
#pragma unroll
                for (int j = 0; j < 8; ++j) {
                    int jp = j >> 1, rr = (j & 1) * 2;
                    mma16816(acc[i][j], fah[i], fbh[jp][rr], fbh[jp][rr + 1]);
                    mma16816(acc[i][j], fah[i], fbl[jp][rr], fbl[jp][rr + 1]);
                    mma16816(acc[i][j], fal[i], fbh[jp][rr], fbh[jp][rr + 1]);
                }
        }
        __syncthreads();
    }

    const int g = lid >> 2, t = lid & 3;

    // Fused RoPE for Q/K (MODE 0, z<2): lane holds cols d and d+32 at j, j+4.
    if (MODE == 0 && z < 2) {
#pragma unroll
        for (int i = 0; i < 2; ++i) {
#pragma unroll
            for (int half = 0; half < 2; ++half) {
                int row = bm * 128 + wm + 16 * i + g + half * 8;
                int s = row & (S_ - 1);
#pragma unroll
                for (int j = 0; j < 4; ++j) {
#pragma unroll
                    for (int e = 0; e < 2; ++e) {
                        int dd = 8 * j + 2 * t + e;   // < 32
                        float cs = g_cosT[s * 32 + dd];
                        float sn = g_sinT[s * 32 + dd];
                        float x1 = acc[i][j][2 * half + e];
                        float x2 = acc[i][j + 4][2 * half + e];
                        acc[i][j][2 * half + e]     = x1 * cs - x2 * sn;
                        acc[i][j + 4][2 * half + e] = x2 * cs + x1 * sn;
                    }
                }
            }
        }
    }

#pragma unroll
    for (int i = 0; i < 2; ++i) {
#pragma unroll
        for (int j = 0; j < 8; ++j) {
            int row0 = bm * 128 + wm + 16 * i + g;
            int n = bn * 128 + wn + 8 * j + 2 * t;
#pragma unroll
            for (int half = 0; half < 2; ++half) {
                int row = row0 + half * 8;
                float2 v = make_float2(acc[i][j][half * 2 + 0],
                                       acc[i][j][half * 2 + 1]);
                if (MODE == 0) {
                    int bb = row >> 11;
                    int ss = row & (S_ - 1);
                    int hh = n >> 6;
                    int dd = n & 63;
                    __nv_bfloat16 h0 = __float2bfloat16(v.x);
                    __nv_bfloat16 h1 = __float2bfloat16(v.y);
                    __nv_bfloat16 l0 = __float2bfloat16(v.x - __bfloat162float(h0));
                    __nv_bfloat16 l1 = __float2bfloat16(v.y - __bfloat162float(h1));
                    size_t tile = (size_t)((bb * H_ + hh) * 32 + (ss >> 6)) * 4096;
                    if (z < 2) {
                        float* dst = (z == 0) ? g_q : g_k;
                        *(float2*)(dst + (((size_t)(bb * H_ + hh) * S_ + ss) << 6) + dd) = v;
                        __nv_bfloat16* th = (z == 0) ? g_qh : g_kh;
                        __nv_bfloat16* tl = (z == 0) ? g_ql : g_kl;
                        uint32_t sw = sw128((uint32_t)((ss & 63) * 128 + dd * 2));
                        *(__nv_bfloat162*)(th + tile + (sw >> 1)) = __nv_bfloat162(h0, h1);
                        *(__nv_bfloat162*)(tl + tile + (sw >> 1)) = __nv_bfloat162(l0, l1);
                    } else {
                        // V: transposed [d][key] bf16 tiles only
                        int rr2 = ss & 63;
                        uint32_t sw0 = sw128((uint32_t)(dd * 128 + rr2 * 2));
                        uint32_t sw1 = sw128((uint32_t)((dd + 1) * 128 + rr2 * 2));
                        g_vth[tile + (sw0 >> 1)] = h0;
                        g_vtl[tile + (sw0 >> 1)] = l0;
                        g_vth[tile + (sw1 >> 1)] = h1;
                        g_vtl[tile + (sw1 >> 1)] = l1;
                    }
                } else {
                    *(float2*)(out + (size_t)row * HID_ + n) = v;
                }
            }
        }
    }
}

// ---------------------------------------------------------------------------
// Block representatives: mean of roped K over 256-token blocks.  512 threads.
// ---------------------------------------------------------------------------
__global__ __launch_bounds__(512) void brep_kernel() {
    __shared__ float red[8][64];
    int blk = blockIdx.x;          // bh*8 + nb
    int bh = blk >> 3;
    int nbk = blk & 7;
    int d = threadIdx.x & 63;
    int qd = threadIdx.x >> 6;     // 0..7
    const float* kp = g_k + ((size_t)bh * S_ + nbk * BS_ + qd * 32) * 64 + d;
    float sum = 0.0f;
#pragma unroll 8
    for (int i = 0; i < 32; ++i) sum += kp[(size_t)i * 64];
    red[qd][d] = sum;
    __syncthreads();
    if (qd == 0) {
        float t = 0.0f;
#pragma unroll
        for (int i = 0; i < 8; ++i) t += red[i][d];
        g_brep[(size_t)blk * 64 + d] = t * (1.0f / 256.0f);
    }
}

// ---------------------------------------------------------------------------
// Top-3 selection: 128 threads, one query per thread.  Q read in 16-float
// chunks (registers only — no Qsh, no spills); Bsh 2KB.
// ---------------------------------------------------------------------------
__global__ __launch_bounds__(128) void select_kernel() {
    __shared__ float Bsh[NB_ * 64];
    const int tid = threadIdx.x;
    const int qidx = blockIdx.x * 128 + tid;
    const int bh = qidx >> 11;

    for (int off = tid; off < NB_ * 64; off += 128)
        Bsh[off] = g_brep[(size_t)bh * (NB_ * 64) + off];
    __syncthreads();

    int s = qidx & (S_ - 1);
    int cur = s >> 8;

    float sc[NB_];
#pragma unroll
    for (int j = 0; j < NB_; ++j) sc[j] = 0.0f;

    const float4* qp = (const float4*)(g_q + (size_t)qidx * 64);
#pragma unroll
    for (int seg = 0; seg < 4; ++seg) {
        float qb[16];
#pragma unroll
        for (int i = 0; i < 4; ++i) {
            float4 v = qp[seg * 4 + i];
            qb[i * 4 + 0] = v.x;
            qb[i * 4 + 1] = v.y;
            qb[i * 4 + 2] = v.z;
            qb[i * 4 + 3] = v.w;
        }
#pragma unroll
        for (int j = 0; j < NB_; ++j) {
#pragma unroll
            for (int d = 0; d < 16; ++d)
                sc[j] = fmaf(qb[d], Bsh[j * 64 + seg * 16 + d], sc[j]);
        }
    }
#pragma unroll
    for (int j = 0; j < NB_; ++j) {
        if (j > cur) sc[j] = -INFINITY;
        else if (j == cur) sc[j] = 3.402823466e38f;
    }

    unsigned msk = 0;
    bool used[NB_];
#pragma unroll
    for (int j = 0; j < NB_; ++j) used[j] = false;
#pragma unroll
    for (int t = 0; t < TK_; ++t) {
        int bi = -1; float bv = 0.0f;
#pragma unroll
        for (int j = 0; j < NB_; ++j) {
            if (!used[j] && (bi < 0 || sc[j] > bv)) { bi = j; bv = sc[j]; }
        }
        used[bi] = true;
        msk |= 1u << bi;
    }
    g_mask[qidx] = (unsigned char)msk;
}

// ---------------------------------------------------------------------------
// Sparse flash attention on HMMA (bf16x3), cp.async double-buffered K/V.
// EXACT round-9/round-12 kernel: 64 queries per CTA, 128 threads.
// grid = (32, 12, 2), qt reversed.
// smem 64KB: Q (16KB) overlays KV stage 0; 2 stages x 32KB.
// ---------------------------------------------------------------------------
#define A_STAGE 32768
#define ATTN_SMEM (2 * A_STAGE)

__global__ __launch_bounds__(128) void attn_kernel() {
    extern __shared__ char smem[];
    const uint32_t sb = smem_u32(smem);
    const int tid = threadIdx.x;
    const int wid = tid >> 5, lid = tid & 31;
    const int qt = (int)(gridDim.x - 1 - blockIdx.x);   // heavy tiles first
    const int h = blockIdx.y, b = blockIdx.z;
    const int q0 = qt * 64;
    const int bh = b * H_ + h;
    const int wq = wid * 16;

    // Load Q tiles into stage-0 region (consumed into fragments before reuse)
    {
        const uint4* s0 = (const uint4*)(g_qh + (size_t)(bh * 32 + qt) * 4096);
        const uint4* s1 = (const uint4*)(g_ql + (size_t)(bh * 32 + qt) * 4096);
        uint4* d0 = (uint4*)(smem);
        uint4* d1 = (uint4*)(smem + 8192);
#pragma unroll
        for (int i = 0; i < 4; ++i) {
            int o = tid + i * 128;
            d0[o] = s0[o];
            d1[o] = s1[o];
        }
    }
    __syncthreads();

    const int a_row = lid & 15;
    const int a_k8 = (lid >> 4) << 3;
    const int b_row = (lid & 7) + ((lid >> 4) << 3);
    const int b_k8 = ((lid >> 3) & 1) << 3;
    uint32_t fqh[4][4], fql[4][4];
#pragma unroll
    for (int ks = 0; ks < 4; ++ks) {
        uint32_t sw = sw128((uint32_t)((wq + a_row) * 128 + (ks * 16 + a_k8) * 2));
        ldmatrix_x4(fqh[ks][0], fqh[ks][1], fqh[ks][2], fqh[ks][3], sb + sw);
        ldmatrix_x4(fql[ks][0], fql[ks][1], fql[ks][2], fql[ks][3], sb + 8192 + sw);
    }
    __syncthreads();   // all warps done reading Q before stage 0 is overwritten

    const int g = lid >> 2;
    const int qq = (lid & 3) * 2;
    const int r0 = q0 + wq + g;
    const int r1 = r0 + 8;
    const unsigned msk0 = g_mask[(size_t)bh * S_ + r0];
    const unsigned msk1 = g_mask[(size_t)bh * S_ + r1];

    const int cur = q0 >> 8;
    const int nkt = ((cur >= 2) ? (cur + 1) : 3) * 4;

    float mrow0 = -INFINITY, mrow1 = -INFINITY, lrow0 = 0.0f, lrow1 = 0.0f;
    float acc_o[8][4];
#pragma unroll
    for (int j = 0; j < 8; ++j)
#pragma unroll
        for (int r = 0; r < 4; ++r) acc_o[j][r] = 0.0f;

    auto issue_kv = [&](int kt, int st) {
        size_t tb = (size_t)(bh * 32 + kt) * 4096;
        uint32_t base = sb + st * A_STAGE;
        const char* s0 = (const char*)(g_kh + tb);
        const char* s1 = (const char*)(g_kl + tb);
        const char* s2 = (const char*)(g_vth + tb);
        const char* s3 = (const char*)(g_vtl + tb);
#pragma unroll
        for (int i = 0; i < 4; ++i) {
            int o = (tid + i * 128) * 16;
            cp_async16(base + 0 + o, s0 + o);
            cp_async16(base + 8192 + o, s1 + o);
            cp_async16(base + 16384 + o, s2 + o);
            cp_async16(base + 24576 + o, s3 + o);
        }
    };

    issue_kv(0, 0);
    CP_COMMIT();

    for (int kt = 0; kt < nkt; ++kt) {
        const int k0 = kt * 64;
        const int jb = kt >> 2;
        const int st = kt & 1;
        if (kt + 1 < nkt) {
            issue_kv(kt + 1, (kt + 1) & 1);
            CP_COMMIT();
            CP_WAIT1();
        } else {
            CP_WAIT0();
        }
        __syncthreads();
        const uint32_t kb = sb + st * A_STAGE;

        // S = Q K^T (bf16x3)
        float s[8][4];
#pragma unroll
        for (int j = 0; j < 8; ++j)
#pragma unroll
            for (int r = 0; r < 4; ++r) s[j][r] = 0.0f;
#pragma unroll
        for (int ks = 0; ks < 4; ++ks) {
            uint32_t fkh[4][4], fkl[4][4];
#pragma unroll
            for (int jp = 0; jp < 4; ++jp) {
                uint32_t sw = sw128((uint32_t)((jp * 16 + b_row) * 128 +
                                               (ks * 16 + b_k8) * 2));
                ldmatrix_x4(fkh[jp][0], fkh[jp][1], fkh[jp][2], fkh[jp][3],
                            kb + 0 + sw);
                ldmatrix_x4(fkl[jp][0], fkl[jp][1], fkl[jp][2], fkl[jp][3],
                            kb + 8192 + sw);
            }
#pragma unroll
            for (int j = 0; j < 8; ++j) {
                int jp = j >> 1, rr = (j & 1) * 2;
                mma16816(s[j], fqh[ks], fkh[jp][rr], fkh[jp][rr + 1]);
                mma16816(s[j], fqh[ks], fkl[jp][rr], fkl[jp][rr + 1]);
                mma16816(s[j], fql[ks], fkh[jp][rr], fkh[jp][rr + 1]);
            }
        }

        // Mask + scale + online softmax (round-9 form)
        const bool sel0 = (msk0 >> jb) & 1u;
        const bool sel1 = (msk1 >> jb) & 1u;
        float mx0 = -INFINITY, mx1 = -INFINITY;
#pragma unroll
        for (int j = 0; j < 8; ++j) {
#pragma unroll
            for (int e = 0; e < 2; ++e) {
                int kg = k0 + j * 8 + qq + e;
                bool v0 = sel0 && (jb != cur || kg <= r0);
                bool v1 = sel1 && (jb != cur || kg <= r1);
                float s0v = v0 ? s[j][e] * 0.125f : -INFINITY;
                float s1v = v1 ? s[j][2 + e] * 0.125f : -INFINITY;
                s[j][e] = s0v;
                s[j][2 + e] = s1v;
                mx0 = fmaxf(mx0, s0v);
                mx1 = fmaxf(mx1, s1v);
            }
        }
#pragma unroll
        for (int off = 1; off <= 2; off <<= 1) {
            mx0 = fmaxf(mx0, __shfl_xor_sync(0xffffffffu, mx0, off));
            mx1 = fmaxf(mx1, __shfl_xor_sync(0xffffffffu, mx1, off));
        }
        float newm0 = fmaxf(mrow0, mx0);
        float newm1 = fmaxf(mrow1, mx1);
        float fac0 = (mrow0 == -INFINITY) ? 0.0f : __expf(mrow0 - newm0);
        float fac1 = (mrow1 == -INFINITY) ? 0.0f : __expf(mrow1 - newm1);
        float rs0 = 0.0f, rs1 = 0.0f;
#pragma unroll
        for (int j = 0; j < 8; ++j) {
#pragma unroll
            for (int e = 0; e < 2; ++e) {
                float p0 = (s[j][e] == -INFINITY) ? 0.0f : __expf(s[j][e] - newm0);
                float p1 = (s[j][2 + e] == -INFINITY) ? 0.0f : __expf(s[j][2 + e] - newm1);
                s[j][e] = p0;
                s[j][2 + e] = p1;
                rs0 += p0;
                rs1 += p1;
            }
        }
#pragma unroll
        for (int off = 1; off <= 2; off <<= 1) {
            rs0 += __shfl_xor_sync(0xffffffffu, rs0, off);
            rs1 += __shfl_xor_sync(0xffffffffu, rs1, off);
        }
        lrow0 = lrow0 * fac0 + rs0;
        lrow1 = lrow1 * fac1 + rs1;
        mrow0 = newm0;
        mrow1 = newm1;
#pragma unroll
        for (int j = 0; j < 8; ++j) {
            acc_o[j][0] *= fac0;
            acc_o[j][1] *= fac0;
            acc_o[j][2] *= fac1;
            acc_o[j][3] *= fac1;
        }

        // acc_o += P V  (round-9 form: cvt round-trip hi, then lo)
#pragma unroll
        for (int j0 = 0; j0 < 4; ++j0) {
            const int j = 2 * j0;
            float h00 = __bfloat162float(__float2bfloat16(s[j][0]));
            float h01 = __bfloat162float(__float2bfloat16(s[j][1]));
            float h02 = __bfloat162float(__float2bfloat16(s[j][2]));
            float h03 = __bfloat162float(__float2bfloat16(s[j][3]));
            float h10 = __bfloat162float(__float2bfloat16(s[j + 1][0]));
            float h11 = __bfloat162float(__float2bfloat16(s[j + 1][1]));
            float h12 = __bfloat162float(__float2bfloat16(s[j + 1][2]));
            float h13 = __bfloat162float(__float2bfloat16(s[j + 1][3]));
            uint32_t ph[4], pl[4];
            ph[0] = bf16x2_pack(s[j][0], s[j][1]);
            ph[1] = bf16x2_pack(s[j][2], s[j][3]);
            ph[2] = bf16x2_pack(s[j + 1][0], s[j + 1][1]);
            ph[3] = bf16x2_pack(s[j + 1][2], s[j + 1][3]);
            pl[0] = bf16x2_pack(s[j][0] - h00, s[j][1] - h01);
            pl[1] = bf16x2_pack(s[j][2] - h02, s[j][3] - h03);
            pl[2] = bf16x2_pack(s[j + 1][0] - h10, s[j + 1][1] - h11);
            pl[3] = bf16x2_pack(s[j + 1][2] - h12, s[j + 1][3] - h13);

            uint32_t fvh[4][4], fvl[4][4];
#pragma unroll
            for (int jp = 0; jp < 4; ++jp) {
                uint32_t sw = sw128((uint32_t)((jp * 16 + b_row) * 128 +
                                               (j0 * 16 + b_k8) * 2));
                ldmatrix_x4(fvh[jp][0], fvh[jp][1], fvh[jp][2], fvh[jp][3],
                            kb + 16384 + sw);
                ldmatrix_x4(fvl[jp][0], fvl[jp][1], fvl[jp][2], fvl[jp][3],
                            kb + 24576 + sw);
            }
#pragma unroll
            for (int jn = 0; jn < 8; ++jn) {
                int jp = jn >> 1, rr = (jn & 1) * 2;
                mma16816(acc_o[jn], ph, fvh[jp][rr], fvh[jp][rr + 1]);
                mma16816(acc_o[jn], ph, fvl[jp][rr], fvl[jp][rr + 1]);
                mma16816(acc_o[jn], pl, fvh[jp][rr], fvh[jp][rr + 1]);
            }
        }
        __syncthreads();
    }

    // Epilogue: normalize, split to bf16 hi/lo, write O-proj A-tiles directly.
    float inv0 = 1.0f / lrow0;
    float inv1 = 1.0f / lrow1;
#pragma unroll
    for (int j = 0; j < 8; ++j) {
        int n = j * 8 + qq;              // 0..63, even
#pragma unroll
        for (int half = 0; half < 2; ++half) {
            int rg = b * S_ + (half ? r1 : r0);     // token row
            float inv = half ? inv1 : inv0;
            float vx = acc_o[j][half * 2 + 0] * inv;
            float vy = acc_o[j][half * 2 + 1] * inv;
            __nv_bfloat16 h0 = __float2bfloat16(vx);
            __nv_bfloat16 h1 = __float2bfloat16(vy);
            __nv_bfloat16 l0 = __float2bfloat16(vx - __bfloat162float(h0));
            __nv_bfloat16 l1 = __float2bfloat16(vy - __bfloat162float(h1));
            int mtile = rg >> 7;
            int r = rg & 127;
            uint32_t sw = sw128((uint32_t)(r * 128 + n * 2));
            size_t dst_half = (size_t)(mtile * NCHUNK_ + h) * 8192 + (sw >> 1);
            *(__nv_bfloat162*)(g_ah + dst_half) = __nv_bfloat162(h0, h1);
            *(__nv_bfloat162*)(g_al + dst_half) = __nv_bfloat162(l0, l1);
        }
    }
}

// ---------------------------------------------------------------------------
extern "C" void kernel_launch(void* const* d_in, const int* in_sizes, int n_in,
                              void* d_out, int out_size) {
    const float* hidden = (const float*)d_in[0];
    const float* Wq = (const float*)d_in[1];
    const float* Wk = (const float*)d_in[2];
    const float* Wv = (const float*)d_in[3];
    const float* Wo = (const float*)d_in[4];

    static bool attr_done = false;
    if (!attr_done) {
        cudaFuncSetAttribute(mma_gemm_kernel<0>,
                             cudaFuncAttributeMaxDynamicSharedMemorySize,
                             GEMM_SMEM_BYTES);
        cudaFuncSetAttribute(mma_gemm_kernel<1>,
                             cudaFuncAttributeMaxDynamicSharedMemorySize,
                             GEMM_SMEM_BYTES);
        cudaFuncSetAttribute(attn_kernel,
                             cudaFuncAttributeMaxDynamicSharedMemorySize,
                             ATTN_SMEM);
        attr_done = true;
    }

    // Conversion + sin/cos tables in ONE launch
    conv_all_kernel<<<(N_CONV_TOTAL + S_ * 32 + 255) / 256, 256>>>(
        hidden, Wq, Wk, Wv, Wo);

    // QKV projections (HMMA): fused RoPE, bf16 attn tiles, V transposed bf16
    mma_gemm_kernel<0><<<dim3(HID_ / 128, M_ / 128, 3), 256, GEMM_SMEM_BYTES>>>(nullptr);

    brep_kernel<<<B_ * H_ * NB_, 512>>>();
    select_kernel<<<B_ * H_ * S_ / 128, 128>>>();

    attn_kernel<<<dim3(S_ / 64, H_, B_), 128, ATTN_SMEM>>>();

    // O projection straight from attention's bf16 tiles into d_out
    mma_gemm_kernel<1><<<dim3(HID_ / 128, M_ / 128), 256, GEMM_SMEM_BYTES>>>((float*)d_out);
}